// round 13
// baseline (speedup 1.0000x reference)
#include <cuda_runtime.h>
#include <cuda_bf16.h>
#include <cuda_fp16.h>
#include <cstdint>

// Problem shape (fixed by reference)
#define BB 4
#define HH 16
#define SS 2048
#define DD 64
#define TQ 16            // queries per CTA
#define KC 64            // keys per fused chunk
#define NCHUNK (SS/KC)   // 32
#define NT 256
#define SCALE 0.125f

#define EPW 1028         // e-plane row stride, words (1028 % 32 == 4)
#define KPS 72           // K plane row stride (72 % 32 == 8), rows = d2 (32)
#define VPS 36           // V plane row stride (36 % 32 == 4), rows = d (64)
#define OBS 68           // O reduction buffer row stride (floats)

#define OUT_ELEMS (BB*HH*SS*DD)

#define W_EP  16448      // 16 * 1028
#define W_KPL 2304       // 32 * 72
#define W_VPL 2304       // 64 * 36
#define SMEM_WORDS (W_EP + 2*W_KPL + 2*W_VPL + TQ*DD + 128 + 16)
#define SMEM_BYTES (SMEM_WORDS * 4)     // ~107 KB -> 2 CTAs/SM

// D(16x8 f32) += A(16x16 bf16, row) * B(16x8 bf16, col)
#define MMA16(d, a0, a1, a2, a3, b0, b1)                                       \
    asm volatile(                                                              \
        "mma.sync.aligned.m16n8k16.row.col.f32.bf16.bf16.f32 "                 \
        "{%0,%1,%2,%3},{%4,%5,%6,%7},{%8,%9},{%0,%1,%2,%3};"                   \
        : "+f"(d[0]), "+f"(d[1]), "+f"(d[2]), "+f"(d[3])                       \
        : "r"(a0), "r"(a1), "r"(a2), "r"(a3), "r"(b0), "r"(b1))

// D(16x8 f32) += A(16x8 f16, row) * B(8x8 f16, col)
#define MMAH8(d, a0, a1, b0)                                                   \
    asm volatile(                                                              \
        "mma.sync.aligned.m16n8k8.row.col.f32.f16.f16.f32 "                    \
        "{%0,%1,%2,%3},{%4,%5},{%6},{%0,%1,%2,%3};"                            \
        : "+f"(d[0]), "+f"(d[1]), "+f"(d[2]), "+f"(d[3])                       \
        : "r"(a0), "r"(a1), "r"(b0))

// split (x,y) into packed bf16x2 hi and lo planes
__device__ __forceinline__ void bsplit2(float x, float y, uint32_t& hi, uint32_t& lo) {
    __nv_bfloat162 H = __floats2bfloat162_rn(x, y);
    float2 hf = __bfloat1622float2(H);
    __nv_bfloat162 L = __floats2bfloat162_rn(x - hf.x, y - hf.y);
    hi = *reinterpret_cast<uint32_t*>(&H);
    lo = *reinterpret_cast<uint32_t*>(&L);
}

// split (x,y) into packed f16x2 hi and lo planes
__device__ __forceinline__ void hsplit2(float x, float y, uint32_t& hi, uint32_t& lo) {
    __half2 H = __floats2half2_rn(x, y);
    float2 hf = __half22float2(H);
    __half2 L = __floats2half2_rn(x - hf.x, y - hf.y);
    hi = *reinterpret_cast<uint32_t*>(&H);
    lo = *reinterpret_cast<uint32_t*>(&L);
}

__device__ __forceinline__ uint32_t packh2(float x, float y) {
    __half2 v = __floats2half2_rn(x, y);
    return *reinterpret_cast<uint32_t*>(&v);
}

__global__ __launch_bounds__(NT, 2)
void sdpa_v4(const float* __restrict__ Q, const float* __restrict__ K,
             const float* __restrict__ V, const int* __restrict__ mask,
             float* __restrict__ out, float* __restrict__ wts) {
    extern __shared__ uint32_t sm[];
    uint32_t* EP = sm;                 // e-plane: 16 x 1028 (fp16 pairs) — for W only
    uint32_t* KH = sm + W_EP;          // 32 x 72
    uint32_t* KL = KH + W_KPL;
    uint32_t* VH = KL + W_KPL;         // 64 x 36
    uint32_t* VL = VH + W_VPL;
    float* Qs   = (float*)(VL + W_VPL);    // 16 x 64 raw Q
    float* part = Qs + TQ * DD;            // [16][8]
    float* invs = part + 128;              // [16]
    float* Obuf = (float*)KH;              // overlays planes after main loop (8*1088)

    const int h  = blockIdx.x;
    const int q0 = blockIdx.y * TQ;
    const int b  = blockIdx.z;

    const int tid = threadIdx.x;
    const int w   = tid >> 5;   // warp 0..7 (owns keys 8w..8w+7 of each chunk)
    const int l   = tid & 31;
    const int g   = l >> 2;     // 0..7
    const int tg  = l & 3;      // 0..3

    const size_t bh = (size_t)(b * HH + h);
    const float* Qb = Q + bh * SS * DD + (size_t)q0 * DD;
    const float* Kb = K + bh * SS * DD;
    const float* Vb = V + bh * SS * DD;
    const int*   Mb = mask + (size_t)b * SS * SS + (size_t)q0 * SS;
    float* Ob = out + bh * SS * DD + (size_t)q0 * DD;
    float* Wb = wts + bh * SS * SS + (size_t)q0 * SS;

    ((float4*)Qs)[tid] = ((const float4*)Qb)[tid];
    __syncthreads();

    // Q fragments: bf16 hi/lo split, SCALE folded (held all of the main loop)
    uint32_t Qh[4][4], Ql[4][4];
#pragma unroll
    for (int dk = 0; dk < 4; dk++) {
        const int base = 16 * dk + 2 * tg;
        float2 p00 = *(const float2*)&Qs[g * DD + base];
        float2 p10 = *(const float2*)&Qs[(g + 8) * DD + base];
        float2 p01 = *(const float2*)&Qs[g * DD + base + 8];
        float2 p11 = *(const float2*)&Qs[(g + 8) * DD + base + 8];
        bsplit2(p00.x * SCALE, p00.y * SCALE, Qh[dk][0], Ql[dk][0]);
        bsplit2(p10.x * SCALE, p10.y * SCALE, Qh[dk][1], Ql[dk][1]);
        bsplit2(p01.x * SCALE, p01.y * SCALE, Qh[dk][2], Ql[dk][2]);
        bsplit2(p11.x * SCALE, p11.y * SCALE, Qh[dk][3], Ql[dk][3]);
    }

    float s0 = 0.f, s1 = 0.f;                 // row-sum partials (rows g, g+8)
    float oacc[8][4];                          // partial O: 16q x 64d (this warp's keys)
#pragma unroll
    for (int nt = 0; nt < 8; nt++) {
        oacc[nt][0] = 0.f; oacc[nt][1] = 0.f; oacc[nt][2] = 0.f; oacc[nt][3] = 0.f;
    }

    // ================= fused main loop over 64-key chunks ==================
    for (int c = 0; c < NCHUNK; c++) {
        const int cbase = c * KC;
        __syncthreads();    // planes free of previous chunk's readers

        // ---- stage K chunk: warp w owns keys 8w..8w+7, lane = d-pair -------
#pragma unroll
        for (int j = 0; j < 8; j++) {
            const int key = 8 * w + j;
            float2 kv = *(const float2*)&Kb[(size_t)(cbase + key) * DD + 2 * l];
            uint32_t hi, lo;
            bsplit2(kv.x, kv.y, hi, lo);
            const int wi = l * KPS + (key ^ ((l >> 2) & 7));
            KH[wi] = hi;
            KL[wi] = lo;
        }
        // ---- stage V chunk (transposed): warp w owns key-pairs 4w..4w+3 ----
#pragma unroll
        for (int j = 0; j < 4; j++) {
            const int k2 = 4 * w + j;
#pragma unroll
            for (int p = 0; p < 2; p++) {
                const int d = l + 32 * p;
                float va  = Vb[(size_t)(cbase + 2 * k2) * DD + d];
                float vb2 = Vb[(size_t)(cbase + 2 * k2 + 1) * DD + d];
                uint32_t hi, lo;
                hsplit2(va, vb2, hi, lo);
                const int wi = d * VPS + (k2 ^ ((d >> 3) & 3));
                VH[wi] = hi;
                VL[wi] = lo;
            }
        }
        __syncthreads();

        // mask for this warp's 8 keys (in flight during MMAs)
        const int mc = cbase + 8 * w + 2 * tg;
        int2 m0 = *(const int2*)&Mb[(size_t)g * SS + mc];
        int2 m1 = *(const int2*)&Mb[(size_t)(g + 8) * SS + mc];

        // ---- QK^T: warp w x its 8 keys, 16 rows, 3x bf16 split -------------
        float acc[4] = {0.f, 0.f, 0.f, 0.f};
        const int key = 8 * w + g;
#pragma unroll
        for (int dk = 0; dk < 4; dk++) {
            const int d2a = 8 * dk + tg, d2b = d2a + 4;
            const int sa = (2 * dk) & 7, sb = (2 * dk + 1) & 7;
            const int ia = d2a * KPS + (key ^ sa);
            const int ib = d2b * KPS + (key ^ sb);
            uint32_t bh0 = KH[ia], bh1 = KH[ib];
            uint32_t bl0 = KL[ia], bl1 = KL[ib];
            MMA16(acc, Qh[dk][0], Qh[dk][1], Qh[dk][2], Qh[dk][3], bh0, bh1);
            MMA16(acc, Qh[dk][0], Qh[dk][1], Qh[dk][2], Qh[dk][3], bl0, bl1);
            MMA16(acc, Ql[dk][0], Ql[dk][1], Ql[dk][2], Ql[dk][3], bh0, bh1);
        }

        // ---- epilogue: mask -> exp; e stays in regs as PV A-fragment -------
        float e0 = m0.x ? __expf(acc[0]) : 0.f;
        float e1 = m0.y ? __expf(acc[1]) : 0.f;
        float e2 = m1.x ? __expf(acc[2]) : 0.f;
        float e3 = m1.y ? __expf(acc[3]) : 0.f;
        uint32_t a0 = packh2(e0, e1);   // = P[g][2tg..2tg+1]   (local keys)
        uint32_t a1 = packh2(e2, e3);   // = P[g+8][2tg..2tg+1]
        const int wc = c * 32 + 4 * w + tg;
        EP[g * EPW + wc]       = a0;    // kept only for the weights output
        EP[(g + 8) * EPW + wc] = a1;
        s0 += e0 + e1;
        s1 += e2 + e3;

        // ---- PV: partial O(16x64) += P(16x8) * V(8x64), f16 2-term ---------
#pragma unroll
        for (int nt = 0; nt < 8; nt++) {
            const int vi = (8 * nt + g) * VPS + ((4 * w + tg) ^ (nt & 3));
            uint32_t vh = VH[vi], vl = VL[vi];
            MMAH8(oacc[nt], a0, a1, vh);
            MMAH8(oacc[nt], a0, a1, vl);
        }
    }

    // ================= row-sum reduction -> invs[16] =======================
    s0 += __shfl_xor_sync(0xffffffffu, s0, 1);
    s0 += __shfl_xor_sync(0xffffffffu, s0, 2);
    s1 += __shfl_xor_sync(0xffffffffu, s1, 1);
    s1 += __shfl_xor_sync(0xffffffffu, s1, 2);
    if (tg == 0) {
        part[g * 8 + w]       = s0;
        part[(g + 8) * 8 + w] = s1;
    }
    __syncthreads();   // also: all PV plane reads done -> Obuf may overlay

    // ---- stage per-warp partial O tiles into smem --------------------------
#pragma unroll
    for (int nt = 0; nt < 8; nt++) {
        const int col = 8 * nt + 2 * tg;
        *(float2*)&Obuf[w * 1088 + g * OBS + col] =
            make_float2(oacc[nt][0], oacc[nt][1]);
        *(float2*)&Obuf[w * 1088 + (g + 8) * OBS + col] =
            make_float2(oacc[nt][2], oacc[nt][3]);
    }
    if (tid < 16) {   // overlap invs computation with Obuf stores
        float t = 0.f;
#pragma unroll
        for (int j = 0; j < 8; j++) t += part[tid * 8 + j];
        invs[tid] = 1.0f / t;
    }
    __syncthreads();

    // ---- cross-warp O reduction + normalized write -------------------------
    {
        const int q  = tid >> 4;          // 0..15
        const int d0 = (tid & 15) * 4;    // 0..60
        float4 s = make_float4(0.f, 0.f, 0.f, 0.f);
#pragma unroll
        for (int ww = 0; ww < 8; ww++) {
            float4 v = *(const float4*)&Obuf[ww * 1088 + q * OBS + d0];
            s.x += v.x; s.y += v.y; s.z += v.z; s.w += v.w;
        }
        const float iv = invs[q];
        *(float4*)&Ob[(size_t)q * DD + d0] =
            make_float4(s.x * iv, s.y * iv, s.z * iv, s.w * iv);
    }

    // ================= normalized weights to global ========================
#pragma unroll
    for (int rr = 0; rr < 2; rr++) {
        const int r = 2 * w + rr;
        const float inv = invs[r];
#pragma unroll
        for (int j = 0; j < 8; j++) {
            uint4 u = *(const uint4*)&EP[r * EPW + 4 * (l + 32 * j)];
            float2 f0 = __half22float2(*reinterpret_cast<__half2*>(&u.x));
            float2 f1 = __half22float2(*reinterpret_cast<__half2*>(&u.y));
            float2 f2 = __half22float2(*reinterpret_cast<__half2*>(&u.z));
            float2 f3 = __half22float2(*reinterpret_cast<__half2*>(&u.w));
            float* dst = &Wb[(size_t)r * SS + 8 * (l + 32 * j)];
            *(float4*)dst       = make_float4(f0.x * inv, f0.y * inv, f1.x * inv, f1.y * inv);
            *(float4*)(dst + 4) = make_float4(f2.x * inv, f2.y * inv, f3.x * inv, f3.y * inv);
        }
    }
}

extern "C" void kernel_launch(void* const* d_in, const int* in_sizes, int n_in,
                              void* d_out, int out_size) {
    (void)in_sizes; (void)n_in; (void)out_size;
    const float* Q    = (const float*)d_in[0];
    const float* K    = (const float*)d_in[1];
    const float* V    = (const float*)d_in[2];
    const int*   mask = (const int*)d_in[3];
    float* out = (float*)d_out;
    float* wts = out + OUT_ELEMS;

    static int smem_set = 0;
    if (!smem_set) {
        cudaFuncSetAttribute(sdpa_v4,
                             cudaFuncAttributeMaxDynamicSharedMemorySize,
                             SMEM_BYTES);
        smem_set = 1;
    }

    dim3 grid(HH, SS / TQ, BB);  // h fastest -> mask tile reused across heads in L2
    sdpa_v4<<<grid, NT, SMEM_BYTES>>>(Q, K, V, mask, out, wts);
}

// round 15
// speedup vs baseline: 1.1032x; 1.1032x over previous
#include <cuda_runtime.h>
#include <cuda_bf16.h>
#include <cuda_fp16.h>
#include <cstdint>

// Problem shape (fixed by reference)
#define BB 4
#define HH 16
#define SS 2048
#define DD 64
#define TQ 16            // queries per CTA
#define KC 128           // keys per fused chunk
#define NCHUNK (SS/KC)   // 16
#define NT 256
#define SCALE 0.125f

#define EPW 1028         // e-plane row stride, words (1028 % 32 == 4)
#define KPS 136          // K plane row stride (136 % 32 == 8), rows = d2 (32)
#define VPS 68           // V plane row stride (68 % 32 == 4),  rows = d (64), 64 key-pairs
#define OBS 68           // O reduction buffer row stride (floats)

#define OUT_ELEMS (BB*HH*SS*DD)

#define W_EP  16448      // 16 * 1028
#define W_KPL 4352       // 32 * 136
#define W_VPL 4352       // 64 * 68
#define SMEM_WORDS (W_EP + 2*W_KPL + 2*W_VPL + TQ*DD + 128 + 16)
#define SMEM_BYTES (SMEM_WORDS * 4)     // ~140 KB -> still fine for 1x, need <113.6KB for 2x? no:
// 227KB/2 = 113.6KB per CTA for 2 CTAs/SM. 140KB too big! Use shared K/V plane (V overlays K? no,
// both needed same chunk). Reduce: drop EP? needed for W. -> overlay EP rows progressively? No.
// Fix: stage V hi only + reconstruct? No. Instead: K planes and V planes both needed.
// 2*4352*2*4 = 69.6KB planes + EP 65.8KB + Q 4KB = 140KB. Must cut EP: store e as fp16 in
// HALF the words? EP already fp16 pairs (2 bytes/e): 16*2048*2B = 64KB. Can't shrink further
// without hurting W accuracy. Alternative: shrink K/V planes by reusing K plane space for V:
// K is consumed by QK MMAs before PV runs; but staging V must happen before barrier 2.
// Solution: 3 barriers/chunk: stage K, sync, QK+epi, sync, stage V into SAME planes, sync, PV.
// That's R13's barrier count. Instead: keep 2 CTAs/SM by using KC=64 for V granularity?
// Simplest working compromise: KC=128 with V planes overlaying EP tail is unsafe.
// -> Use single shared plane pair sized for K (4352w) and stage V into it AFTER QK, with one
//    extra barrier (3/chunk = 48 total, still < R13's 64, and saves 34.8KB -> total ~105KB -> 2 CTAs/SM).

// D(16x8 f32) += A(16x16 bf16, row) * B(16x8 bf16, col)
#define MMA16(d, a0, a1, a2, a3, b0, b1)                                       \
    asm volatile(                                                              \
        "mma.sync.aligned.m16n8k16.row.col.f32.bf16.bf16.f32 "                 \
        "{%0,%1,%2,%3},{%4,%5,%6,%7},{%8,%9},{%0,%1,%2,%3};"                   \
        : "+f"(d[0]), "+f"(d[1]), "+f"(d[2]), "+f"(d[3])                       \
        : "r"(a0), "r"(a1), "r"(a2), "r"(a3), "r"(b0), "r"(b1))

// D(16x8 f32) += A(16x16 f16, row) * B(16x8 f16, col)
#define MMAH(d, a0, a1, a2, a3, b0, b1)                                        \
    asm volatile(                                                              \
        "mma.sync.aligned.m16n8k16.row.col.f32.f16.f16.f32 "                   \
        "{%0,%1,%2,%3},{%4,%5,%6,%7},{%8,%9},{%0,%1,%2,%3};"                   \
        : "+f"(d[0]), "+f"(d[1]), "+f"(d[2]), "+f"(d[3])                       \
        : "r"(a0), "r"(a1), "r"(a2), "r"(a3), "r"(b0), "r"(b1))

#undef SMEM_WORDS
#undef SMEM_BYTES
#define W_PL 4352        // shared plane (K then V), 32*136 = 64*68 = 4352
#define SMEM_WORDS (W_EP + 2*W_PL + TQ*DD + 128 + 16)
#define SMEM_BYTES (SMEM_WORDS * 4)     // ~105.5 KB -> 2 CTAs/SM

// split (x,y) into packed bf16x2 hi and lo planes
__device__ __forceinline__ void bsplit2(float x, float y, uint32_t& hi, uint32_t& lo) {
    __nv_bfloat162 H = __floats2bfloat162_rn(x, y);
    float2 hf = __bfloat1622float2(H);
    __nv_bfloat162 L = __floats2bfloat162_rn(x - hf.x, y - hf.y);
    hi = *reinterpret_cast<uint32_t*>(&H);
    lo = *reinterpret_cast<uint32_t*>(&L);
}

// split (x,y) into packed f16x2 hi and lo planes
__device__ __forceinline__ void hsplit2(float x, float y, uint32_t& hi, uint32_t& lo) {
    __half2 H = __floats2half2_rn(x, y);
    float2 hf = __half22float2(H);
    __half2 L = __floats2half2_rn(x - hf.x, y - hf.y);
    hi = *reinterpret_cast<uint32_t*>(&H);
    lo = *reinterpret_cast<uint32_t*>(&L);
}

__device__ __forceinline__ uint32_t packh2(float x, float y) {
    __half2 v = __floats2half2_rn(x, y);
    return *reinterpret_cast<uint32_t*>(&v);
}

__global__ __launch_bounds__(NT, 2)
void sdpa_v5(const float* __restrict__ Q, const float* __restrict__ K,
             const float* __restrict__ V, const int* __restrict__ mask,
             float* __restrict__ out, float* __restrict__ wts) {
    extern __shared__ uint32_t sm[];
    uint32_t* EP = sm;                 // e-plane: 16 x 1028 (fp16 pairs) — weights only
    uint32_t* PH = sm + W_EP;          // shared plane hi: K (32x136) then V (64x68)
    uint32_t* PL = PH + W_PL;          // shared plane lo
    float* Qs   = (float*)(PL + W_PL);     // 16 x 64 raw Q
    float* part = Qs + TQ * DD;            // [16][8]
    float* invs = part + 128;              // [16]
    float* Obuf = (float*)PH;              // overlays planes after main loop (8*1088 fits 2*4352)

    const int h  = blockIdx.x;
    const int q0 = blockIdx.y * TQ;
    const int b  = blockIdx.z;

    const int tid = threadIdx.x;
    const int w   = tid >> 5;   // warp 0..7 (owns keys 16w..16w+15 of each chunk)
    const int l   = tid & 31;
    const int g   = l >> 2;     // 0..7
    const int tg  = l & 3;      // 0..3

    const size_t bh = (size_t)(b * HH + h);
    const float* Qb = Q + bh * SS * DD + (size_t)q0 * DD;
    const float* Kb = K + bh * SS * DD;
    const float* Vb = V + bh * SS * DD;
    const int*   Mb = mask + (size_t)b * SS * SS + (size_t)q0 * SS;
    float* Ob = out + bh * SS * DD + (size_t)q0 * DD;
    float* Wb = wts + bh * SS * SS + (size_t)q0 * SS;

    ((float4*)Qs)[tid] = ((const float4*)Qb)[tid];
    __syncthreads();

    // Q fragments: bf16 hi/lo split, SCALE folded
    uint32_t Qh[4][4], Ql[4][4];
#pragma unroll
    for (int dk = 0; dk < 4; dk++) {
        const int base = 16 * dk + 2 * tg;
        float2 p00 = *(const float2*)&Qs[g * DD + base];
        float2 p10 = *(const float2*)&Qs[(g + 8) * DD + base];
        float2 p01 = *(const float2*)&Qs[g * DD + base + 8];
        float2 p11 = *(const float2*)&Qs[(g + 8) * DD + base + 8];
        bsplit2(p00.x * SCALE, p00.y * SCALE, Qh[dk][0], Ql[dk][0]);
        bsplit2(p10.x * SCALE, p10.y * SCALE, Qh[dk][1], Ql[dk][1]);
        bsplit2(p01.x * SCALE, p01.y * SCALE, Qh[dk][2], Ql[dk][2]);
        bsplit2(p11.x * SCALE, p11.y * SCALE, Qh[dk][3], Ql[dk][3]);
    }

    float s0 = 0.f, s1 = 0.f;      // row-sum partials (rows g, g+8)
    float oacc[8][4];              // partial O(16x64) over this warp's keys
#pragma unroll
    for (int nt = 0; nt < 8; nt++) {
        oacc[nt][0] = 0.f; oacc[nt][1] = 0.f; oacc[nt][2] = 0.f; oacc[nt][3] = 0.f;
    }

    // ================= fused main loop over 128-key chunks =================
    for (int c = 0; c < NCHUNK; c++) {
        const int cbase = c * KC;
        __syncthreads();   // plane free of previous chunk's PV readers

        // ---- stage K chunk (bf16 hi/lo, transposed, swizzled) --------------
#pragma unroll
        for (int j = 0; j < 16; j++) {
            const int key = 16 * w + j;
            float2 kv = *(const float2*)&Kb[(size_t)(cbase + key) * DD + 2 * l];
            uint32_t hi, lo;
            bsplit2(kv.x, kv.y, hi, lo);
            const int wi = l * KPS + (key ^ ((l >> 2) & 7));
            PH[wi] = hi;
            PL[wi] = lo;
        }
        __syncthreads();

        // mask for this warp's 16 keys (in flight during MMAs)
        const int mc = cbase + 16 * w + 2 * tg;
        int2 m00 = *(const int2*)&Mb[(size_t)g * SS + mc];
        int2 m01 = *(const int2*)&Mb[(size_t)g * SS + mc + 8];
        int2 m10 = *(const int2*)&Mb[(size_t)(g + 8) * SS + mc];
        int2 m11 = *(const int2*)&Mb[(size_t)(g + 8) * SS + mc + 8];

        // ---- QK^T: 16 keys x 16 rows, 3x bf16 split ------------------------
        float acc0[4] = {0.f, 0.f, 0.f, 0.f};
        float acc1[4] = {0.f, 0.f, 0.f, 0.f};
#pragma unroll
        for (int dk = 0; dk < 4; dk++) {
            const int d2a = 8 * dk + tg, d2b = d2a + 4;
            const int sa = (d2a >> 2) & 7, sb = (d2b >> 2) & 7;
#pragma unroll
            for (int jn = 0; jn < 2; jn++) {
                const int key = 16 * w + 8 * jn + g;
                const int ia = d2a * KPS + (key ^ sa);
                const int ib = d2b * KPS + (key ^ sb);
                uint32_t bh0 = PH[ia], bh1 = PH[ib];
                uint32_t bl0 = PL[ia], bl1 = PL[ib];
                float* A = jn ? acc1 : acc0;
                MMA16(A, Qh[dk][0], Qh[dk][1], Qh[dk][2], Qh[dk][3], bh0, bh1);
                MMA16(A, Qh[dk][0], Qh[dk][1], Qh[dk][2], Qh[dk][3], bl0, bl1);
                MMA16(A, Ql[dk][0], Ql[dk][1], Ql[dk][2], Ql[dk][3], bh0, bh1);
            }
        }

        // ---- epilogue: mask -> exp; e packed as PV A-fragment --------------
        const int wc = c * 64 + 8 * w + tg;
        float e0 = m00.x ? __expf(acc0[0]) : 0.f;
        float e1 = m00.y ? __expf(acc0[1]) : 0.f;
        float e2 = m10.x ? __expf(acc0[2]) : 0.f;
        float e3 = m10.y ? __expf(acc0[3]) : 0.f;
        uint32_t a0 = packh2(e0, e1);      // row g,   local k 2tg..2tg+1
        uint32_t a1 = packh2(e2, e3);      // row g+8, local k 2tg..2tg+1
        EP[g * EPW + wc]       = a0;
        EP[(g + 8) * EPW + wc] = a1;
        s0 += e0 + e1; s1 += e2 + e3;
        e0 = m01.x ? __expf(acc1[0]) : 0.f;
        e1 = m01.y ? __expf(acc1[1]) : 0.f;
        e2 = m11.x ? __expf(acc1[2]) : 0.f;
        e3 = m11.y ? __expf(acc1[3]) : 0.f;
        uint32_t a2 = packh2(e0, e1);      // row g,   local k 8+2tg
        uint32_t a3 = packh2(e2, e3);      // row g+8, local k 8+2tg
        EP[g * EPW + wc + 4]       = a2;
        EP[(g + 8) * EPW + wc + 4] = a3;
        s0 += e0 + e1; s1 += e2 + e3;

        __syncthreads();   // all QK reads of K plane done -> reuse for V

        // ---- stage V chunk (f16 hi/lo, transposed VT[d][k2], swizzled) -----
#pragma unroll
        for (int j = 0; j < 8; j++) {
            const int k2 = 8 * w + j;          // key-pair 0..63
#pragma unroll
            for (int p = 0; p < 2; p++) {
                const int d = l + 32 * p;
                float va  = Vb[(size_t)(cbase + 2 * k2) * DD + d];
                float vb2 = Vb[(size_t)(cbase + 2 * k2 + 1) * DD + d];
                uint32_t hi, lo;
                hsplit2(va, vb2, hi, lo);
                const int wi = d * VPS + (k2 ^ ((d >> 3) & 3));
                PH[wi] = hi;
                PL[wi] = lo;
            }
        }
        __syncthreads();

        // ---- PV: O(16x64) += P(16x16) * V(16x64), f16 2-term ---------------
        // B-frags: b0 at local k-pair tg, b1 at tg+4; warp's key-pair base 8w.
#pragma unroll
        for (int nt = 0; nt < 8; nt++) {
            const int d = 8 * nt + g;
            const int sw = nt & 3;             // (d>>3)&3 with d=8nt+g, g<8
            const int i0 = d * VPS + ((8 * w + tg) ^ sw);
            const int i1 = d * VPS + ((8 * w + tg + 4) ^ sw);
            uint32_t vh0 = PH[i0], vh1 = PH[i1];
            uint32_t vl0 = PL[i0], vl1 = PL[i1];
            MMAH(oacc[nt], a0, a1, a2, a3, vh0, vh1);
            MMAH(oacc[nt], a0, a1, a2, a3, vl0, vl1);
        }
    }

    // ================= row-sum reduction -> invs[16] =======================
    s0 += __shfl_xor_sync(0xffffffffu, s0, 1);
    s0 += __shfl_xor_sync(0xffffffffu, s0, 2);
    s1 += __shfl_xor_sync(0xffffffffu, s1, 1);
    s1 += __shfl_xor_sync(0xffffffffu, s1, 2);
    if (tg == 0) {
        part[g * 8 + w]       = s0;
        part[(g + 8) * 8 + w] = s1;
    }
    __syncthreads();   // PV reads done -> Obuf may overlay planes

    // ---- stage per-warp partial O tiles into smem --------------------------
    // oacc[nt]: d0=(row g, col 8nt+2tg), d1=(g, +1), d2=(g+8, 8nt+2tg), d3=(g+8, +1)
#pragma unroll
    for (int nt = 0; nt < 8; nt++) {
        const int col = 8 * nt + 2 * tg;
        *(float2*)&Obuf[w * 1088 + g * OBS + col] =
            make_float2(oacc[nt][0], oacc[nt][1]);
        *(float2*)&Obuf[w * 1088 + (g + 8) * OBS + col] =
            make_float2(oacc[nt][2], oacc[nt][3]);
    }
    if (tid < 16) {
        float t = 0.f;
#pragma unroll
        for (int j = 0; j < 8; j++) t += part[tid * 8 + j];
        invs[tid] = 1.0f / t;
    }
    __syncthreads();

    // ---- cross-warp O reduction + normalized write -------------------------
    {
        const int q  = tid >> 4;          // 0..15
        const int d0 = (tid & 15) * 4;    // 0..60
        float4 s = make_float4(0.f, 0.f, 0.f, 0.f);
#pragma unroll
        for (int ww = 0; ww < 8; ww++) {
            float4 v = *(const float4*)&Obuf[ww * 1088 + q * OBS + d0];
            s.x += v.x; s.y += v.y; s.z += v.z; s.w += v.w;
        }
        const float iv = invs[q];
        *(float4*)&Ob[(size_t)q * DD + d0] =
            make_float4(s.x * iv, s.y * iv, s.z * iv, s.w * iv);
    }

    // ================= normalized weights to global ========================
#pragma unroll
    for (int rr = 0; rr < 2; rr++) {
        const int r = 2 * w + rr;
        const float inv = invs[r];
#pragma unroll
        for (int j = 0; j < 8; j++) {
            uint4 u = *(const uint4*)&EP[r * EPW + 4 * (l + 32 * j)];
            float2 f0 = __half22float2(*reinterpret_cast<__half2*>(&u.x));
            float2 f1 = __half22float2(*reinterpret_cast<__half2*>(&u.y));
            float2 f2 = __half22float2(*reinterpret_cast<__half2*>(&u.z));
            float2 f3 = __half22float2(*reinterpret_cast<__half2*>(&u.w));
            float* dst = &Wb[(size_t)r * SS + 8 * (l + 32 * j)];
            *(float4*)dst       = make_float4(f0.x * inv, f0.y * inv, f1.x * inv, f1.y * inv);
            *(float4*)(dst + 4) = make_float4(f2.x * inv, f2.y * inv, f3.x * inv, f3.y * inv);
        }
    }
}

extern "C" void kernel_launch(void* const* d_in, const int* in_sizes, int n_in,
                              void* d_out, int out_size) {
    (void)in_sizes; (void)n_in; (void)out_size;
    const float* Q    = (const float*)d_in[0];
    const float* K    = (const float*)d_in[1];
    const float* V    = (const float*)d_in[2];
    const int*   mask = (const int*)d_in[3];
    float* out = (float*)d_out;
    float* wts = out + OUT_ELEMS;

    static int smem_set = 0;
    if (!smem_set) {
        cudaFuncSetAttribute(sdpa_v5,
                             cudaFuncAttributeMaxDynamicSharedMemorySize,
                             SMEM_BYTES);
        smem_set = 1;
    }

    dim3 grid(HH, SS / TQ, BB);  // h fastest -> mask tile reused across heads in L2
    sdpa_v5<<<grid, NT, SMEM_BYTES>>>(Q, K, V, mask, out, wts);
}